// round 8
// baseline (speedup 1.0000x reference)
#include <cuda_runtime.h>
#include <cuda_fp16.h>
#include <cstdint>

// Problem constants
#define Bb  2
#define Tt  2048
#define Ee  1024
#define Hh  8
#define Dd  512
#define HDc 4096          // H*D
#define Mc  4096          // B*T
#define Dh  256           // D/2

// fp16 scratch (static device allocations)
__device__ __align__(1024) __half g_xh[(size_t)Mc * Ee];
__device__ __align__(1024) __half g_wqh[(size_t)HDc * Ee];
__device__ __align__(1024) __half g_wkh[(size_t)HDc * Ee];
__device__ __align__(1024) __half g_wvh[(size_t)HDc * Ee];
__device__ __align__(1024) __half g_woh[(size_t)Ee * HDc];
__device__ __align__(1024) __half g_qh[(size_t)Mc * HDc];
__device__ __align__(1024) __half g_kh[(size_t)Mc * HDc];
__device__ __align__(1024) __half g_vTh[(size_t)HDc * Mc];     // [h*D, b*T]
__device__ __align__(1024) __half g_attnh[(size_t)Mc * HDc];
__device__ __align__(1024) __half g_sh[(size_t)Bb * Hh * Tt * Tt];   // 128 MiB
__device__ float g_cos[Tt * Dh];
__device__ float g_sin[Tt * Dh];

// ---------------------------------------------------------------------------
// PTX helpers
// ---------------------------------------------------------------------------
__device__ __forceinline__ uint32_t smem_u32(const void* p) {
    uint32_t a;
    asm("{ .reg .u64 t; cvta.to.shared.u64 t, %1; cvt.u32.u64 %0, t; }" : "=r"(a) : "l"(p));
    return a;
}
__device__ __forceinline__ void cpasync16(uint32_t dst, const void* src) {
    asm volatile("cp.async.cg.shared.global [%0], [%1], 16;" :: "r"(dst), "l"(src));
}
#define CP_COMMIT() asm volatile("cp.async.commit_group;" ::: "memory")
#define CP_WAIT4()  asm volatile("cp.async.wait_group 4;" ::: "memory")

__device__ __forceinline__ void ldsm4(uint32_t& r0, uint32_t& r1, uint32_t& r2, uint32_t& r3,
                                      uint32_t addr) {
    asm volatile("ldmatrix.sync.aligned.m8n8.x4.shared.b16 {%0,%1,%2,%3}, [%4];"
                 : "=r"(r0), "=r"(r1), "=r"(r2), "=r"(r3) : "r"(addr));
}
__device__ __forceinline__ void mma168(float (&c)[4], const uint32_t (&a)[4], const uint32_t (&b)[2]) {
    asm volatile(
        "mma.sync.aligned.m16n8k16.row.col.f32.f16.f16.f32 "
        "{%0,%1,%2,%3}, {%4,%5,%6,%7}, {%8,%9}, {%0,%1,%2,%3};\n"
        : "+f"(c[0]), "+f"(c[1]), "+f"(c[2]), "+f"(c[3])
        : "r"(a[0]), "r"(a[1]), "r"(a[2]), "r"(a[3]), "r"(b[0]), "r"(b[1]));
}

// Swizzled smem offset for a (row, 16B-chunk): 64B rows, chunk XOR (r>>1)&3.
__device__ __forceinline__ uint32_t swz(int r, int c) {
    return (uint32_t)(r * 64 + ((c ^ ((r >> 1) & 3)) << 4));
}

// ---------------------------------------------------------------------------
// fp16 tensor-core GEMM:  C = alpha * A[M,K] * B[N,K]^T   (both K-major, NT)
// CSKIP: skip tiles with n0 >= m0+128 (causal; exact diagonal cover at N=256)
// CK: limit K to m0+128.  OUT16: store C as fp16 (else fp32).
// CTA tile 128x256x32, 256 threads, 8 warps (2m x 4n), warp tile 64x64,
// 6-stage cp.async pipeline, swizzled 64B smem rows, one sync per k-chunk.
// Batch over blockIdx.z: off = (z>>3)*Outer + (z&7)*Inner.
// ---------------------------------------------------------------------------
#define NSTG   6
#define STG_B  24576                        // A 128*64 + B 256*64
#define GEMM_SMEM (NSTG * STG_B)            // 147456

template <bool CSKIP, bool CK, bool OUT16>
__global__ __launch_bounds__(256, 1) void gemm_fp16(
    const __half* __restrict__ Ag, const __half* __restrict__ Bg, void* __restrict__ Cg,
    int Kdim, int lda, int ldb, int ldc,
    long long aO, long long aI, long long bO, long long bI, long long cO, long long cI,
    float alpha)
{
    const int m0 = blockIdx.y * 128;
    const int n0 = blockIdx.x * 256;
    if (CSKIP && n0 >= m0 + 128) return;

    const int z = blockIdx.z;
    const __half* A = Ag + (long long)(z >> 3) * aO + (long long)(z & 7) * aI;
    const __half* B = Bg + (long long)(z >> 3) * bO + (long long)(z & 7) * bI;

    const int kLim = CK ? ((Kdim < m0 + 128) ? Kdim : (m0 + 128)) : Kdim;
    const int nk = kLim >> 5;

    extern __shared__ char smem[];
    const uint32_t sb = smem_u32(smem);
    const int tid = threadIdx.x, wid = tid >> 5, lane = tid & 31;
    const int wm = wid & 1, wn = wid >> 1;

    // cp.async: A 512 chunks (16B), B 1024 chunks; 256 threads
    const int ldr = tid >> 2;                // row 0..63 (+64/+128/+192)
    const int ldc4 = tid & 3;                // 16B chunk 0..3
    auto load_stage = [&](int kt) {
        uint32_t stA = sb + (kt % NSTG) * STG_B;
        uint32_t stB = stA + 8192;
        const __half* Asrc = A + (size_t)m0 * lda + kt * 32;
        const __half* Bsrc = B + (size_t)n0 * ldb + kt * 32;
#pragma unroll
        for (int p = 0; p < 2; p++) {
            int r = ldr + p * 64;
            cpasync16(stA + swz(r, ldc4), Asrc + (size_t)r * lda + ldc4 * 8);
        }
#pragma unroll
        for (int p = 0; p < 4; p++) {
            int r = ldr + p * 64;
            cpasync16(stB + swz(r, ldc4), Bsrc + (size_t)r * ldb + ldc4 * 8);
        }
    };

#pragma unroll
    for (int s = 0; s < NSTG - 1; s++) { if (s < nk) load_stage(s); CP_COMMIT(); }

    float acc[4][8][4] = {};

    const int lrow = lane & 15;              // row within 16-row ldmatrix group
    const int chHalf = lane >> 4;            // 16B half within 32B k-slice

    for (int kt = 0; kt < nk; kt++) {
        CP_WAIT4();
        __syncthreads();
        if (kt + NSTG - 1 < nk) load_stage(kt + NSTG - 1);
        CP_COMMIT();

        uint32_t stA = sb + (kt % NSTG) * STG_B;
        uint32_t stB = stA + 8192;
#pragma unroll
        for (int kk = 0; kk < 2; kk++) {
            const int ch = kk * 2 + chHalf;
            uint32_t a[4][4], b[8][2];
#pragma unroll
            for (int i = 0; i < 4; i++) {
                int r = wm * 64 + i * 16 + lrow;
                ldsm4(a[i][0], a[i][1], a[i][2], a[i][3], stA + swz(r, ch));
            }
#pragma unroll
            for (int jp = 0; jp < 4; jp++) {
                int r = wn * 64 + jp * 16 + lrow;
                uint32_t t0, t1, t2, t3;
                ldsm4(t0, t1, t2, t3, stB + swz(r, ch));
                b[jp * 2][0] = t0; b[jp * 2 + 1][0] = t1;
                b[jp * 2][1] = t2; b[jp * 2 + 1][1] = t3;
            }
#pragma unroll
            for (int i = 0; i < 4; i++)
#pragma unroll
                for (int j = 0; j < 8; j++) mma168(acc[i][j], a[i], b[j]);
        }
    }

    // epilogue: direct global stores from accumulators
    const int er = lane >> 2, ec = (lane & 3) * 2;
    if (OUT16) {
        __half* C = (__half*)Cg + (long long)(z >> 3) * cO + (long long)(z & 7) * cI;
#pragma unroll
        for (int i = 0; i < 4; i++) {
            int r0 = m0 + wm * 64 + i * 16 + er;
#pragma unroll
            for (int j = 0; j < 8; j++) {
                int c0 = n0 + wn * 64 + j * 8 + ec;
                __half2 h01 = __floats2half2_rn(acc[i][j][0] * alpha, acc[i][j][1] * alpha);
                __half2 h23 = __floats2half2_rn(acc[i][j][2] * alpha, acc[i][j][3] * alpha);
                *(__half2*)(C + (size_t)r0 * ldc + c0) = h01;
                *(__half2*)(C + (size_t)(r0 + 8) * ldc + c0) = h23;
            }
        }
    } else {
        float* C = (float*)Cg + (long long)(z >> 3) * cO + (long long)(z & 7) * cI;
#pragma unroll
        for (int i = 0; i < 4; i++) {
            int r0 = m0 + wm * 64 + i * 16 + er;
#pragma unroll
            for (int j = 0; j < 8; j++) {
                int c0 = n0 + wn * 64 + j * 8 + ec;
                *(float2*)(C + (size_t)r0 * ldc + c0) =
                    make_float2(acc[i][j][0] * alpha, acc[i][j][1] * alpha);
                *(float2*)(C + (size_t)(r0 + 8) * ldc + c0) =
                    make_float2(acc[i][j][2] * alpha, acc[i][j][3] * alpha);
            }
        }
    }
}

// ---------------------------------------------------------------------------
// fp32 -> fp16 conversion
// ---------------------------------------------------------------------------
__global__ void f2h(const float4* __restrict__ in, uint2* __restrict__ outp, int n4) {
    int i = blockIdx.x * 256 + threadIdx.x;
    if (i < n4) {
        float4 v = in[i];
        __half2 a = __floats2half2_rn(v.x, v.y);
        __half2 b = __floats2half2_rn(v.z, v.w);
        outp[i] = make_uint2(*(uint32_t*)&a, *(uint32_t*)&b);
    }
}

// ---------------------------------------------------------------------------
// RoPE (fast-math-immune)
// ---------------------------------------------------------------------------
__device__ __forceinline__ void sincos_cw(float a, float* sp, float* cp) {
    float j = rintf(a * 0.63661977236758138f);
    int   q = (int)j;
    float r = fmaf(j, -1.5707962512969971e+00f, a);
    r = fmaf(j, -7.5497894158615964e-08f, r);
    r = fmaf(j, -5.3903029534742385e-15f, r);
    float x2 = r * r;
    float s = r * (1.f + x2 * (-1.6666667e-1f + x2 * (8.3333333e-3f +
                    x2 * (-1.9841270e-4f + x2 * 2.7557319e-6f))));
    float c = 1.f + x2 * (-0.5f + x2 * (4.1666667e-2f +
                    x2 * (-1.3888889e-3f + x2 * 2.4801587e-5f)));
    switch (q & 3) {
        case 0: *sp =  s; *cp =  c; break;
        case 1: *sp =  c; *cp = -s; break;
        case 2: *sp = -s; *cp = -c; break;
        default:*sp = -c; *cp =  s; break;
    }
}

__global__ void rope_table() {
    int idx = blockIdx.x * 256 + threadIdx.x;
    int d = idx & 255, t = idx >> 8;
    float e = (float)d * (1.0f / 256.0f);
    const float LH = 13.287712097167969f;
    const float LL = 2.8238148e-7f;
    float p = -fmaf(e, LH, e * LL);
    float nf = floorf(p);
    float f  = p - nf;
    float y  = f * 0.69314718055994531f;
    float er = 1.f + y * (1.f + y * (0.5f + y * (0.16666667f + y * (0.041666667f +
               y * (0.0083333333f + y * (0.0013888889f + y * (1.9841270e-4f +
               y * (2.4801587e-5f + y * 2.7557319e-6f))))))));
    float invf = er * __int_as_float(((int)nf + 127) << 23);
    float ang = (float)t * invf;
    float s, c;
    sincos_cw(ang, &s, &c);
    g_cos[idx] = c;
    g_sin[idx] = s;
}

// In-place RoPE on fp16 q and k (flat [b*T+t, h*D+d]), half-split pairs.
__global__ void rope_apply() {
    int idx = blockIdx.x * 256 + threadIdx.x;   // B*T*H*Dh
    int d = idx & 255;
    int h = (idx >> 8) & 7;
    int t = (idx >> 11) & 2047;
    int b = idx >> 22;
    float cc = g_cos[t * 256 + d], ss = g_sin[t * 256 + d];
    size_t base = ((size_t)(b * Tt + t)) * HDc + h * Dd + d;
    float x1 = __half2float(g_qh[base]), x2 = __half2float(g_qh[base + 256]);
    g_qh[base]       = __float2half_rn(x1 * cc - x2 * ss);
    g_qh[base + 256] = __float2half_rn(x1 * ss + x2 * cc);
    x1 = __half2float(g_kh[base]); x2 = __half2float(g_kh[base + 256]);
    g_kh[base]       = __float2half_rn(x1 * cc - x2 * ss);
    g_kh[base + 256] = __float2half_rn(x1 * ss + x2 * cc);
}

// ---------------------------------------------------------------------------
// Causal softmax on fp16 S; zero-pads probs to this row's 128 boundary.
// ---------------------------------------------------------------------------
__global__ void softmax_causal(__half2* __restrict__ S) {
    long long rr = blockIdx.x;
    long long zz = rr >> 11;
    int i = (int)(rr & 2047);
    __half2* row = S + zz * (Tt * Tt / 2) + (size_t)i * (Tt / 2);
    const int L = i + 1;
    const int tid = threadIdx.x;
    __shared__ float red[256];

    float v[8];
    float mx = -3.4e38f;
#pragma unroll
    for (int p = 0; p < 4; p++) {
        int j2 = tid + p * 256;
        float2 f = __half22float2(row[j2]);
        v[p * 2]     = (2 * j2     < L) ? f.x : -3.4e38f;
        v[p * 2 + 1] = (2 * j2 + 1 < L) ? f.y : -3.4e38f;
        mx = fmaxf(mx, fmaxf(v[p * 2], v[p * 2 + 1]));
    }
    red[tid] = mx; __syncthreads();
    for (int s = 128; s > 0; s >>= 1) {
        if (tid < s) red[tid] = fmaxf(red[tid], red[tid + s]);
        __syncthreads();
    }
    mx = red[0]; __syncthreads();

    float sum = 0.f;
#pragma unroll
    for (int p = 0; p < 8; p++) {
        float e = (v[p] > -1e38f) ? expf(v[p] - mx) : 0.f;
        v[p] = e;
        sum += e;
    }
    red[tid] = sum; __syncthreads();
    for (int s = 128; s > 0; s >>= 1) {
        if (tid < s) red[tid] += red[tid + s];
        __syncthreads();
    }
    float inv = 1.0f / red[0];

    const int Lpad = (L + 127) & ~127;
#pragma unroll
    for (int p = 0; p < 4; p++) {
        int j2 = tid + p * 256;
        if (2 * j2 < Lpad)
            row[j2] = __floats2half2_rn(v[p * 2] * inv, v[p * 2 + 1] * inv);
    }
}

// ---------------------------------------------------------------------------
extern "C" void kernel_launch(void* const* d_in, const int* in_sizes, int n_in,
                              void* d_out, int out_size) {
    const float* x  = (const float*)d_in[0];
    const float* Wq = (const float*)d_in[1];
    const float* Wk = (const float*)d_in[2];
    const float* Wv = (const float*)d_in[3];
    const float* Wo = (const float*)d_in[4];
    float* out = (float*)d_out;

    __half *xh, *wqh, *wkh, *wvh, *woh, *qh, *kh, *vTh, *attnh, *sh;
    cudaGetSymbolAddress((void**)&xh, g_xh);
    cudaGetSymbolAddress((void**)&wqh, g_wqh);
    cudaGetSymbolAddress((void**)&wkh, g_wkh);
    cudaGetSymbolAddress((void**)&wvh, g_wvh);
    cudaGetSymbolAddress((void**)&woh, g_woh);
    cudaGetSymbolAddress((void**)&qh, g_qh);
    cudaGetSymbolAddress((void**)&kh, g_kh);
    cudaGetSymbolAddress((void**)&vTh, g_vTh);
    cudaGetSymbolAddress((void**)&attnh, g_attnh);
    cudaGetSymbolAddress((void**)&sh, g_sh);

    cudaFuncSetAttribute(gemm_fp16<false, false, true>,
                         cudaFuncAttributeMaxDynamicSharedMemorySize, GEMM_SMEM);
    cudaFuncSetAttribute(gemm_fp16<true, false, true>,
                         cudaFuncAttributeMaxDynamicSharedMemorySize, GEMM_SMEM);
    cudaFuncSetAttribute(gemm_fp16<false, true, true>,
                         cudaFuncAttributeMaxDynamicSharedMemorySize, GEMM_SMEM);
    cudaFuncSetAttribute(gemm_fp16<false, false, false>,
                         cudaFuncAttributeMaxDynamicSharedMemorySize, GEMM_SMEM);

    dim3 blk(256);
    const long long TT  = (long long)Tt * Tt;
    const long long THD = (long long)Tt * HDc;

    // 0) convert raw fp32 inputs to fp16 scratch
    const int n4 = HDc * Ee / 4;
    f2h<<<n4 / 256, 256>>>((const float4*)x,  (uint2*)xh,  n4);
    f2h<<<n4 / 256, 256>>>((const float4*)Wq, (uint2*)wqh, n4);
    f2h<<<n4 / 256, 256>>>((const float4*)Wk, (uint2*)wkh, n4);
    f2h<<<n4 / 256, 256>>>((const float4*)Wv, (uint2*)wvh, n4);
    f2h<<<n4 / 256, 256>>>((const float4*)Wo, (uint2*)woh, n4);

    // 1) QKV projections (NT)
    gemm_fp16<false, false, true><<<dim3(16, 32, 1), blk, GEMM_SMEM>>>(
        xh, wqh, qh, Ee, Ee, Ee, HDc, 0, 0, 0, 0, 0, 0, 1.f);
    gemm_fp16<false, false, true><<<dim3(16, 32, 1), blk, GEMM_SMEM>>>(
        xh, wkh, kh, Ee, Ee, Ee, HDc, 0, 0, 0, 0, 0, 0, 1.f);
    // vT[hd, m] = Wv[hd,:] . x[m,:]
    gemm_fp16<false, false, true><<<dim3(16, 32, 1), blk, GEMM_SMEM>>>(
        wvh, xh, vTh, Ee, Ee, Ee, Mc, 0, 0, 0, 0, 0, 0, 1.f);

    // 2) RoPE on q, k
    rope_table<<<(Tt * Dh) / 256, 256>>>();
    rope_apply<<<(Bb * Tt * Hh * Dh) / 256, 256>>>();

    // 3) scores[b,h] = scale * q[b,h] @ k[b,h]^T   (causal tile skip)
    gemm_fp16<true, false, true><<<dim3(8, 16, Bb * Hh), blk, GEMM_SMEM>>>(
        qh, kh, sh, Dd, HDc, HDc, Tt,
        THD, (long long)Dd, THD, (long long)Dd,
        (long long)Hh * TT, TT, 0.044194173824159216f);

    // 4) causal softmax (fp16 in/out)
    softmax_causal<<<Bb * Hh * Tt, 256>>>((__half2*)sh);

    // 5) attn[b,h] = P[b,h] @ vT[b,h]^T   (NT, causal K limit)
    gemm_fp16<false, true, true><<<dim3(2, 16, Bb * Hh), blk, GEMM_SMEM>>>(
        sh, vTh, attnh, Tt, Tt, Mc, HDc,
        (long long)Hh * TT, TT,
        (long long)Tt, (long long)Dd * Mc,
        (long long)Tt * HDc, (long long)Dd, 1.f);

    // 6) out = attn_flat @ Wo^T  (fp32 output)
    gemm_fp16<false, false, false><<<dim3(4, 32, 1), blk, GEMM_SMEM>>>(
        attnh, woh, out, HDc, HDc, HDc, Ee, 0, 0, 0, 0, 0, 0, 1.f);
}

// round 9
// speedup vs baseline: 1.1949x; 1.1949x over previous
#include <cuda_runtime.h>
#include <cuda_fp16.h>
#include <cstdint>

// Problem constants
#define Bb  2
#define Tt  2048
#define Ee  1024
#define Hh  8
#define Dd  512
#define HDc 4096          // H*D
#define Mc  4096          // B*T
#define Dh  256           // D/2

// fp16 scratch (static device allocations)
__device__ __align__(1024) __half g_xh[(size_t)Mc * Ee];
__device__ __align__(1024) __half g_wqh[(size_t)HDc * Ee];
__device__ __align__(1024) __half g_wkh[(size_t)HDc * Ee];
__device__ __align__(1024) __half g_wvh[(size_t)HDc * Ee];
__device__ __align__(1024) __half g_woh[(size_t)Ee * HDc];
__device__ __align__(1024) __half g_qh[(size_t)Mc * HDc];
__device__ __align__(1024) __half g_kh[(size_t)Mc * HDc];
__device__ __align__(1024) __half g_vTh[(size_t)HDc * Mc];     // [h*D, b*T]
__device__ __align__(1024) __half g_attnh[(size_t)Mc * HDc];
__device__ __align__(1024) __half g_sh[(size_t)Bb * Hh * Tt * Tt];   // 128 MiB
__device__ float g_cos[Tt * Dh];
__device__ float g_sin[Tt * Dh];

// ---------------------------------------------------------------------------
// PTX helpers
// ---------------------------------------------------------------------------
__device__ __forceinline__ uint32_t smem_u32(const void* p) {
    uint32_t a;
    asm("{ .reg .u64 t; cvta.to.shared.u64 t, %1; cvt.u32.u64 %0, t; }" : "=r"(a) : "l"(p));
    return a;
}
__device__ __forceinline__ void cpasync16(uint32_t dst, const void* src) {
    asm volatile("cp.async.cg.shared.global [%0], [%1], 16;" :: "r"(dst), "l"(src));
}
#define CP_COMMIT() asm volatile("cp.async.commit_group;" ::: "memory")
#define CP_WAIT1()  asm volatile("cp.async.wait_group 1;" ::: "memory")

__device__ __forceinline__ void ldsm4(uint32_t& r0, uint32_t& r1, uint32_t& r2, uint32_t& r3,
                                      uint32_t addr) {
    asm volatile("ldmatrix.sync.aligned.m8n8.x4.shared.b16 {%0,%1,%2,%3}, [%4];"
                 : "=r"(r0), "=r"(r1), "=r"(r2), "=r"(r3) : "r"(addr));
}
__device__ __forceinline__ void mma168(float (&c)[4], const uint32_t (&a)[4], const uint32_t (&b)[2]) {
    asm volatile(
        "mma.sync.aligned.m16n8k16.row.col.f32.f16.f16.f32 "
        "{%0,%1,%2,%3}, {%4,%5,%6,%7}, {%8,%9}, {%0,%1,%2,%3};\n"
        : "+f"(c[0]), "+f"(c[1]), "+f"(c[2]), "+f"(c[3])
        : "r"(a[0]), "r"(a[1]), "r"(a[2]), "r"(a[3]), "r"(b[0]), "r"(b[1]));
}

// Swizzled smem offset for (row, 16B-chunk), 128B rows, full 8-way XOR:
// conflict-free for cp.async STS (one row per 8 lanes) and for each 8-row
// ldmatrix phase (chunks c^0..c^7 all distinct).
__device__ __forceinline__ uint32_t swz(int r, int c) {
    return (uint32_t)(r * 128 + ((c ^ (r & 7)) << 4));
}

// ---------------------------------------------------------------------------
// fp16 tensor-core GEMM:  C = alpha * A[M,K] * B[N,K]^T   (both K-major, NT)
// CSKIP: skip tiles strictly above causal diagonal.  CK: limit K to m0+128.
// OUT16: store C as fp16 (else fp32).
// CTA tile 128x128, K-chunk 64, 256 threads, 8 warps (2m x 4n), warp 64x32,
// 3-stage cp.async pipeline (32KB/stage), one sync per 64-K chunk, 2 CTAs/SM.
// Batch over blockIdx.z: off = (z>>3)*Outer + (z&7)*Inner.
// ---------------------------------------------------------------------------
#define NSTG   3
#define STG_B  32768                        // A 128*128B + B 128*128B
#define GEMM_SMEM (NSTG * STG_B)            // 98304 -> 2 CTAs/SM (192KB)

template <bool CSKIP, bool CK, bool OUT16>
__global__ __launch_bounds__(256, 2) void gemm_fp16(
    const __half* __restrict__ Ag, const __half* __restrict__ Bg, void* __restrict__ Cg,
    int Kdim, int lda, int ldb, int ldc,
    long long aO, long long aI, long long bO, long long bI, long long cO, long long cI,
    float alpha)
{
    const int m0 = blockIdx.y * 128;
    const int n0 = blockIdx.x * 128;
    if (CSKIP && n0 >= m0 + 128) return;

    const int z = blockIdx.z;
    const __half* A = Ag + (long long)(z >> 3) * aO + (long long)(z & 7) * aI;
    const __half* B = Bg + (long long)(z >> 3) * bO + (long long)(z & 7) * bI;

    const int kLim = CK ? ((Kdim < m0 + 128) ? Kdim : (m0 + 128)) : Kdim;
    const int nk = kLim >> 6;               // 64-wide K chunks

    extern __shared__ char smem[];
    const uint32_t sb = smem_u32(smem);
    const int tid = threadIdx.x, wid = tid >> 5, lane = tid & 31;
    const int wm = wid & 1, wn = wid >> 1;

    // cp.async: A 1024 16B-chunks + B 1024; 256 threads x 4 each per half
    const int ldr = tid >> 3;                // row group 0..31 (x4 -> 128 rows)
    const int ldc8 = tid & 7;                // 16B chunk 0..7 within 128B row
    auto load_stage = [&](int kt) {
        uint32_t stA = sb + (kt % NSTG) * STG_B;
        uint32_t stB = stA + 16384;
        const __half* Asrc = A + (size_t)m0 * lda + kt * 64;
        const __half* Bsrc = B + (size_t)n0 * ldb + kt * 64;
#pragma unroll
        for (int p = 0; p < 4; p++) {
            int r = ldr + p * 32;
            cpasync16(stA + swz(r, ldc8), Asrc + (size_t)r * lda + ldc8 * 8);
        }
#pragma unroll
        for (int p = 0; p < 4; p++) {
            int r = ldr + p * 32;
            cpasync16(stB + swz(r, ldc8), Bsrc + (size_t)r * ldb + ldc8 * 8);
        }
    };

#pragma unroll
    for (int s = 0; s < NSTG - 1; s++) { if (s < nk) load_stage(s); CP_COMMIT(); }

    float acc[4][4][4] = {};

    const int lrow = lane & 15;              // row within 16-row ldmatrix group
    const int chHalf = lane >> 4;            // 16B half within 32B k-slice

    for (int kt = 0; kt < nk; kt++) {
        CP_WAIT1();
        __syncthreads();
        if (kt + NSTG - 1 < nk) load_stage(kt + NSTG - 1);
        CP_COMMIT();

        uint32_t stA = sb + (kt % NSTG) * STG_B;
        uint32_t stB = stA + 16384;
#pragma unroll
        for (int kk = 0; kk < 4; kk++) {
            const int ch = kk * 2 + chHalf;
            uint32_t a[4][4], b[4][2];
#pragma unroll
            for (int i = 0; i < 4; i++) {
                int r = wm * 64 + i * 16 + lrow;
                ldsm4(a[i][0], a[i][1], a[i][2], a[i][3], stA + swz(r, ch));
            }
#pragma unroll
            for (int jp = 0; jp < 2; jp++) {
                int r = wn * 32 + jp * 16 + lrow;
                uint32_t t0, t1, t2, t3;
                ldsm4(t0, t1, t2, t3, stB + swz(r, ch));
                b[jp * 2][0] = t0; b[jp * 2 + 1][0] = t1;
                b[jp * 2][1] = t2; b[jp * 2 + 1][1] = t3;
            }
#pragma unroll
            for (int i = 0; i < 4; i++)
#pragma unroll
                for (int j = 0; j < 4; j++) mma168(acc[i][j], a[i], b[j]);
        }
    }

    // epilogue: direct global stores from accumulators
    const int er = lane >> 2, ec = (lane & 3) * 2;
    if (OUT16) {
        __half* C = (__half*)Cg + (long long)(z >> 3) * cO + (long long)(z & 7) * cI;
#pragma unroll
        for (int i = 0; i < 4; i++) {
            int r0 = m0 + wm * 64 + i * 16 + er;
#pragma unroll
            for (int j = 0; j < 4; j++) {
                int c0 = n0 + wn * 32 + j * 8 + ec;
                __half2 h01 = __floats2half2_rn(acc[i][j][0] * alpha, acc[i][j][1] * alpha);
                __half2 h23 = __floats2half2_rn(acc[i][j][2] * alpha, acc[i][j][3] * alpha);
                *(__half2*)(C + (size_t)r0 * ldc + c0) = h01;
                *(__half2*)(C + (size_t)(r0 + 8) * ldc + c0) = h23;
            }
        }
    } else {
        float* C = (float*)Cg + (long long)(z >> 3) * cO + (long long)(z & 7) * cI;
#pragma unroll
        for (int i = 0; i < 4; i++) {
            int r0 = m0 + wm * 64 + i * 16 + er;
#pragma unroll
            for (int j = 0; j < 4; j++) {
                int c0 = n0 + wn * 32 + j * 8 + ec;
                *(float2*)(C + (size_t)r0 * ldc + c0) =
                    make_float2(acc[i][j][0] * alpha, acc[i][j][1] * alpha);
                *(float2*)(C + (size_t)(r0 + 8) * ldc + c0) =
                    make_float2(acc[i][j][2] * alpha, acc[i][j][3] * alpha);
            }
        }
    }
}

// ---------------------------------------------------------------------------
// fused fp32 -> fp16 conversion for all 5 input tensors (one launch)
// Each tensor is 4M elements = 1M float4; blockIdx.x/4096 selects the tensor.
// ---------------------------------------------------------------------------
__global__ void f2h5(const float4* __restrict__ s0, const float4* __restrict__ s1,
                     const float4* __restrict__ s2, const float4* __restrict__ s3,
                     const float4* __restrict__ s4,
                     uint2* __restrict__ d0, uint2* __restrict__ d1,
                     uint2* __restrict__ d2, uint2* __restrict__ d3,
                     uint2* __restrict__ d4) {
    int which = blockIdx.x >> 12;
    int i = (blockIdx.x & 4095) * 256 + threadIdx.x;
    const float4* src = which == 0 ? s0 : which == 1 ? s1 : which == 2 ? s2
                      : which == 3 ? s3 : s4;
    uint2* dst = which == 0 ? d0 : which == 1 ? d1 : which == 2 ? d2
               : which == 3 ? d3 : d4;
    float4 v = src[i];
    __half2 a = __floats2half2_rn(v.x, v.y);
    __half2 b = __floats2half2_rn(v.z, v.w);
    dst[i] = make_uint2(*(uint32_t*)&a, *(uint32_t*)&b);
}

// ---------------------------------------------------------------------------
// RoPE (fast-math-immune)
// ---------------------------------------------------------------------------
__device__ __forceinline__ void sincos_cw(float a, float* sp, float* cp) {
    float j = rintf(a * 0.63661977236758138f);
    int   q = (int)j;
    float r = fmaf(j, -1.5707962512969971e+00f, a);
    r = fmaf(j, -7.5497894158615964e-08f, r);
    r = fmaf(j, -5.3903029534742385e-15f, r);
    float x2 = r * r;
    float s = r * (1.f + x2 * (-1.6666667e-1f + x2 * (8.3333333e-3f +
                    x2 * (-1.9841270e-4f + x2 * 2.7557319e-6f))));
    float c = 1.f + x2 * (-0.5f + x2 * (4.1666667e-2f +
                    x2 * (-1.3888889e-3f + x2 * 2.4801587e-5f)));
    switch (q & 3) {
        case 0: *sp =  s; *cp =  c; break;
        case 1: *sp =  c; *cp = -s; break;
        case 2: *sp = -s; *cp = -c; break;
        default:*sp = -c; *cp =  s; break;
    }
}

__global__ void rope_table() {
    int idx = blockIdx.x * 256 + threadIdx.x;
    int d = idx & 255, t = idx >> 8;
    float e = (float)d * (1.0f / 256.0f);
    const float LH = 13.287712097167969f;
    const float LL = 2.8238148e-7f;
    float p = -fmaf(e, LH, e * LL);
    float nf = floorf(p);
    float f  = p - nf;
    float y  = f * 0.69314718055994531f;
    float er = 1.f + y * (1.f + y * (0.5f + y * (0.16666667f + y * (0.041666667f +
               y * (0.0083333333f + y * (0.0013888889f + y * (1.9841270e-4f +
               y * (2.4801587e-5f + y * 2.7557319e-6f))))))));
    float invf = er * __int_as_float(((int)nf + 127) << 23);
    float ang = (float)t * invf;
    float s, c;
    sincos_cw(ang, &s, &c);
    g_cos[idx] = c;
    g_sin[idx] = s;
}

// In-place RoPE on fp16 q and k (flat [b*T+t, h*D+d]), half-split pairs.
__global__ void rope_apply() {
    int idx = blockIdx.x * 256 + threadIdx.x;   // B*T*H*Dh
    int d = idx & 255;
    int h = (idx >> 8) & 7;
    int t = (idx >> 11) & 2047;
    int b = idx >> 22;
    float cc = g_cos[t * 256 + d], ss = g_sin[t * 256 + d];
    size_t base = ((size_t)(b * Tt + t)) * HDc + h * Dd + d;
    float x1 = __half2float(g_qh[base]), x2 = __half2float(g_qh[base + 256]);
    g_qh[base]       = __float2half_rn(x1 * cc - x2 * ss);
    g_qh[base + 256] = __float2half_rn(x1 * ss + x2 * cc);
    x1 = __half2float(g_kh[base]); x2 = __half2float(g_kh[base + 256]);
    g_kh[base]       = __float2half_rn(x1 * cc - x2 * ss);
    g_kh[base + 256] = __float2half_rn(x1 * ss + x2 * cc);
}

// ---------------------------------------------------------------------------
// Causal softmax on fp16 S; zero-pads probs to this row's 128 boundary.
// ---------------------------------------------------------------------------
__global__ void softmax_causal(__half2* __restrict__ S) {
    long long rr = blockIdx.x;
    long long zz = rr >> 11;
    int i = (int)(rr & 2047);
    __half2* row = S + zz * (Tt * Tt / 2) + (size_t)i * (Tt / 2);
    const int L = i + 1;
    const int tid = threadIdx.x;
    __shared__ float red[256];

    float v[8];
    float mx = -3.4e38f;
#pragma unroll
    for (int p = 0; p < 4; p++) {
        int j2 = tid + p * 256;
        float2 f = __half22float2(row[j2]);
        v[p * 2]     = (2 * j2     < L) ? f.x : -3.4e38f;
        v[p * 2 + 1] = (2 * j2 + 1 < L) ? f.y : -3.4e38f;
        mx = fmaxf(mx, fmaxf(v[p * 2], v[p * 2 + 1]));
    }
    red[tid] = mx; __syncthreads();
    for (int s = 128; s > 0; s >>= 1) {
        if (tid < s) red[tid] = fmaxf(red[tid], red[tid + s]);
        __syncthreads();
    }
    mx = red[0]; __syncthreads();

    float sum = 0.f;
#pragma unroll
    for (int p = 0; p < 8; p++) {
        float e = (v[p] > -1e38f) ? expf(v[p] - mx) : 0.f;
        v[p] = e;
        sum += e;
    }
    red[tid] = sum; __syncthreads();
    for (int s = 128; s > 0; s >>= 1) {
        if (tid < s) red[tid] += red[tid + s];
        __syncthreads();
    }
    float inv = 1.0f / red[0];

    const int Lpad = (L + 127) & ~127;
#pragma unroll
    for (int p = 0; p < 4; p++) {
        int j2 = tid + p * 256;
        if (2 * j2 < Lpad)
            row[j2] = __floats2half2_rn(v[p * 2] * inv, v[p * 2 + 1] * inv);
    }
}

// ---------------------------------------------------------------------------
extern "C" void kernel_launch(void* const* d_in, const int* in_sizes, int n_in,
                              void* d_out, int out_size) {
    const float* x  = (const float*)d_in[0];
    const float* Wq = (const float*)d_in[1];
    const float* Wk = (const float*)d_in[2];
    const float* Wv = (const float*)d_in[3];
    const float* Wo = (const float*)d_in[4];
    float* out = (float*)d_out;

    __half *xh, *wqh, *wkh, *wvh, *woh, *qh, *kh, *vTh, *attnh, *sh;
    cudaGetSymbolAddress((void**)&xh, g_xh);
    cudaGetSymbolAddress((void**)&wqh, g_wqh);
    cudaGetSymbolAddress((void**)&wkh, g_wkh);
    cudaGetSymbolAddress((void**)&wvh, g_wvh);
    cudaGetSymbolAddress((void**)&woh, g_woh);
    cudaGetSymbolAddress((void**)&qh, g_qh);
    cudaGetSymbolAddress((void**)&kh, g_kh);
    cudaGetSymbolAddress((void**)&vTh, g_vTh);
    cudaGetSymbolAddress((void**)&attnh, g_attnh);
    cudaGetSymbolAddress((void**)&sh, g_sh);

    cudaFuncSetAttribute(gemm_fp16<false, false, true>,
                         cudaFuncAttributeMaxDynamicSharedMemorySize, GEMM_SMEM);
    cudaFuncSetAttribute(gemm_fp16<true, false, true>,
                         cudaFuncAttributeMaxDynamicSharedMemorySize, GEMM_SMEM);
    cudaFuncSetAttribute(gemm_fp16<false, true, true>,
                         cudaFuncAttributeMaxDynamicSharedMemorySize, GEMM_SMEM);
    cudaFuncSetAttribute(gemm_fp16<false, false, false>,
                         cudaFuncAttributeMaxDynamicSharedMemorySize, GEMM_SMEM);

    dim3 blk(256);
    const long long TT  = (long long)Tt * Tt;
    const long long THD = (long long)Tt * HDc;

    // 0) convert raw fp32 inputs to fp16 scratch (single fused launch)
    f2h5<<<5 * 4096, 256>>>((const float4*)x, (const float4*)Wq, (const float4*)Wk,
                            (const float4*)Wv, (const float4*)Wo,
                            (uint2*)xh, (uint2*)wqh, (uint2*)wkh,
                            (uint2*)wvh, (uint2*)woh);

    // 1) QKV projections (NT)
    gemm_fp16<false, false, true><<<dim3(32, 32, 1), blk, GEMM_SMEM>>>(
        xh, wqh, qh, Ee, Ee, Ee, HDc, 0, 0, 0, 0, 0, 0, 1.f);
    gemm_fp16<false, false, true><<<dim3(32, 32, 1), blk, GEMM_SMEM>>>(
        xh, wkh, kh, Ee, Ee, Ee, HDc, 0, 0, 0, 0, 0, 0, 1.f);
    // vT[hd, m] = Wv[hd,:] . x[m,:]
    gemm_fp16<false, false, true><<<dim3(32, 32, 1), blk, GEMM_SMEM>>>(
        wvh, xh, vTh, Ee, Ee, Ee, Mc, 0, 0, 0, 0, 0, 0, 1.f);

    // 2) RoPE on q, k
    rope_table<<<(Tt * Dh) / 256, 256>>>();
    rope_apply<<<(Bb * Tt * Hh * Dh) / 256, 256>>>();

    // 3) scores[b,h] = scale * q[b,h] @ k[b,h]^T   (causal tile skip)
    gemm_fp16<true, false, true><<<dim3(16, 16, Bb * Hh), blk, GEMM_SMEM>>>(
        qh, kh, sh, Dd, HDc, HDc, Tt,
        THD, (long long)Dd, THD, (long long)Dd,
        (long long)Hh * TT, TT, 0.044194173824159216f);

    // 4) causal softmax (fp16 in/out)
    softmax_causal<<<Bb * Hh * Tt, 256>>>((__half2*)sh);

    // 5) attn[b,h] = P[b,h] @ vT[b,h]^T   (NT, causal K limit)
    gemm_fp16<false, true, true><<<dim3(4, 16, Bb * Hh), blk, GEMM_SMEM>>>(
        sh, vTh, attnh, Tt, Tt, Mc, HDc,
        (long long)Hh * TT, TT,
        (long long)Tt, (long long)Dd * Mc,
        (long long)Tt * HDc, (long long)Dd, 1.f);

    // 6) out = attn_flat @ Wo^T  (fp32 output)
    gemm_fp16<false, false, false><<<dim3(8, 32, 1), blk, GEMM_SMEM>>>(
        attnh, woh, out, HDc, HDc, HDc, Ee, 0, 0, 0, 0, 0, 0, 1.f);
}

// round 11
// speedup vs baseline: 1.1958x; 1.0008x over previous
#include <cuda_runtime.h>
#include <cuda_fp16.h>
#include <cstdint>

// Problem constants
#define Bb  2
#define Tt  2048
#define Ee  1024
#define Hh  8
#define Dd  512
#define HDc 4096          // H*D
#define Mc  4096          // B*T
#define Dh  256           // D/2

// fp16 scratch (static device allocations)
__device__ __align__(1024) __half g_xh[(size_t)Mc * Ee];
__device__ __align__(1024) __half g_wqkh[(size_t)2 * HDc * Ee];   // [Wq | Wk]
__device__ __align__(1024) __half g_wvh[(size_t)HDc * Ee];
__device__ __align__(1024) __half g_woh[(size_t)Ee * HDc];
__device__ __align__(1024) __half g_qkh[(size_t)2 * Mc * HDc];    // [q | k]
__device__ __align__(1024) __half g_vTh[(size_t)HDc * Mc];        // [h*D, b*T]
__device__ __align__(1024) __half g_attnh[(size_t)Mc * HDc];
__device__ __align__(1024) __half g_sh[(size_t)Bb * Hh * Tt * Tt];   // 128 MiB
__device__ float g_cos[Tt * Dh];
__device__ float g_sin[Tt * Dh];

// ---------------------------------------------------------------------------
// PTX helpers
// ---------------------------------------------------------------------------
__device__ __forceinline__ uint32_t smem_u32(const void* p) {
    uint32_t a;
    asm("{ .reg .u64 t; cvta.to.shared.u64 t, %1; cvt.u32.u64 %0, t; }" : "=r"(a) : "l"(p));
    return a;
}
__device__ __forceinline__ void cpasync16(uint32_t dst, const void* src) {
    asm volatile("cp.async.cg.shared.global [%0], [%1], 16;" :: "r"(dst), "l"(src));
}
#define CP_COMMIT() asm volatile("cp.async.commit_group;" ::: "memory")
#define CP_WAIT1()  asm volatile("cp.async.wait_group 1;" ::: "memory")

__device__ __forceinline__ void ldsm4(uint32_t& r0, uint32_t& r1, uint32_t& r2, uint32_t& r3,
                                      uint32_t addr) {
    asm volatile("ldmatrix.sync.aligned.m8n8.x4.shared.b16 {%0,%1,%2,%3}, [%4];"
                 : "=r"(r0), "=r"(r1), "=r"(r2), "=r"(r3) : "r"(addr));
}
__device__ __forceinline__ void mma168(float (&c)[4], const uint32_t (&a)[4], const uint32_t (&b)[2]) {
    asm volatile(
        "mma.sync.aligned.m16n8k16.row.col.f32.f16.f16.f32 "
        "{%0,%1,%2,%3}, {%4,%5,%6,%7}, {%8,%9}, {%0,%1,%2,%3};\n"
        : "+f"(c[0]), "+f"(c[1]), "+f"(c[2]), "+f"(c[3])
        : "r"(a[0]), "r"(a[1]), "r"(a[2]), "r"(a[3]), "r"(b[0]), "r"(b[1]));
}

// Swizzled smem offset for (row, 16B-chunk), 128B rows, full 8-way XOR.
__device__ __forceinline__ uint32_t swz(int r, int c) {
    return (uint32_t)(r * 128 + ((c ^ (r & 7)) << 4));
}

// ---------------------------------------------------------------------------
// fp16 tensor-core GEMM:  C = alpha * A[M,K] * B[N,K]^T   (both K-major, NT)
// CSKIP: skip tiles strictly above causal diagonal.  CK: limit K to m0+128.
// OUT16: store C as fp16 (else fp32).
// CTA tile 128x128, K-chunk 64, 256 threads, 8 warps (2m x 4n), warp 64x32,
// 3-stage cp.async pipeline (32KB/stage), one sync per 64-K chunk, 2 CTAs/SM.
// Batch over blockIdx.z: off = (z>>3)*Outer + (z&7)*Inner.
// ---------------------------------------------------------------------------
#define NSTG   3
#define STG_B  32768                        // A 128*128B + B 128*128B
#define GEMM_SMEM (NSTG * STG_B)            // 98304 -> 2 CTAs/SM (192KB)

template <bool CSKIP, bool CK, bool OUT16>
__global__ __launch_bounds__(256, 2) void gemm_fp16(
    const __half* __restrict__ Ag, const __half* __restrict__ Bg, void* __restrict__ Cg,
    int Kdim, int lda, int ldb, int ldc,
    long long aO, long long aI, long long bO, long long bI, long long cO, long long cI,
    float alpha)
{
    const int m0 = blockIdx.y * 128;
    const int n0 = blockIdx.x * 128;
    if (CSKIP && n0 >= m0 + 128) return;

    const int z = blockIdx.z;
    const __half* A = Ag + (long long)(z >> 3) * aO + (long long)(z & 7) * aI;
    const __half* B = Bg + (long long)(z >> 3) * bO + (long long)(z & 7) * bI;

    const int kLim = CK ? ((Kdim < m0 + 128) ? Kdim : (m0 + 128)) : Kdim;
    const int nk = kLim >> 6;               // 64-wide K chunks

    extern __shared__ char smem[];
    const uint32_t sb = smem_u32(smem);
    const int tid = threadIdx.x, wid = tid >> 5, lane = tid & 31;
    const int wm = wid & 1, wn = wid >> 1;

    const int ldr = tid >> 3;                // row group 0..31 (x4 -> 128 rows)
    const int ldc8 = tid & 7;                // 16B chunk 0..7 within 128B row
    auto load_stage = [&](int kt) {
        uint32_t stA = sb + (kt % NSTG) * STG_B;
        uint32_t stB = stA + 16384;
        const __half* Asrc = A + (size_t)m0 * lda + kt * 64;
        const __half* Bsrc = B + (size_t)n0 * ldb + kt * 64;
#pragma unroll
        for (int p = 0; p < 4; p++) {
            int r = ldr + p * 32;
            cpasync16(stA + swz(r, ldc8), Asrc + (size_t)r * lda + ldc8 * 8);
        }
#pragma unroll
        for (int p = 0; p < 4; p++) {
            int r = ldr + p * 32;
            cpasync16(stB + swz(r, ldc8), Bsrc + (size_t)r * ldb + ldc8 * 8);
        }
    };

#pragma unroll
    for (int s = 0; s < NSTG - 1; s++) { if (s < nk) load_stage(s); CP_COMMIT(); }

    float acc[4][4][4] = {};

    const int lrow = lane & 15;
    const int chHalf = lane >> 4;

    for (int kt = 0; kt < nk; kt++) {
        CP_WAIT1();
        __syncthreads();
        if (kt + NSTG - 1 < nk) load_stage(kt + NSTG - 1);
        CP_COMMIT();

        uint32_t stA = sb + (kt % NSTG) * STG_B;
        uint32_t stB = stA + 16384;
#pragma unroll
        for (int kk = 0; kk < 4; kk++) {
            const int ch = kk * 2 + chHalf;
            uint32_t a[4][4], b[4][2];
#pragma unroll
            for (int i = 0; i < 4; i++) {
                int r = wm * 64 + i * 16 + lrow;
                ldsm4(a[i][0], a[i][1], a[i][2], a[i][3], stA + swz(r, ch));
            }
#pragma unroll
            for (int jp = 0; jp < 2; jp++) {
                int r = wn * 32 + jp * 16 + lrow;
                uint32_t t0, t1, t2, t3;
                ldsm4(t0, t1, t2, t3, stB + swz(r, ch));
                b[jp * 2][0] = t0; b[jp * 2 + 1][0] = t1;
                b[jp * 2][1] = t2; b[jp * 2 + 1][1] = t3;
            }
#pragma unroll
            for (int i = 0; i < 4; i++)
#pragma unroll
                for (int j = 0; j < 4; j++) mma168(acc[i][j], a[i], b[j]);
        }
    }

    const int er = lane >> 2, ec = (lane & 3) * 2;
    if (OUT16) {
        __half* C = (__half*)Cg + (long long)(z >> 3) * cO + (long long)(z & 7) * cI;
#pragma unroll
        for (int i = 0; i < 4; i++) {
            int r0 = m0 + wm * 64 + i * 16 + er;
#pragma unroll
            for (int j = 0; j < 4; j++) {
                int c0 = n0 + wn * 32 + j * 8 + ec;
                __half2 h01 = __floats2half2_rn(acc[i][j][0] * alpha, acc[i][j][1] * alpha);
                __half2 h23 = __floats2half2_rn(acc[i][j][2] * alpha, acc[i][j][3] * alpha);
                *(__half2*)(C + (size_t)r0 * ldc + c0) = h01;
                *(__half2*)(C + (size_t)(r0 + 8) * ldc + c0) = h23;
            }
        }
    } else {
        float* C = (float*)Cg + (long long)(z >> 3) * cO + (long long)(z & 7) * cI;
#pragma unroll
        for (int i = 0; i < 4; i++) {
            int r0 = m0 + wm * 64 + i * 16 + er;
#pragma unroll
            for (int j = 0; j < 4; j++) {
                int c0 = n0 + wn * 32 + j * 8 + ec;
                *(float2*)(C + (size_t)r0 * ldc + c0) =
                    make_float2(acc[i][j][0] * alpha, acc[i][j][1] * alpha);
                *(float2*)(C + (size_t)(r0 + 8) * ldc + c0) =
                    make_float2(acc[i][j][2] * alpha, acc[i][j][3] * alpha);
            }
        }
    }
}

// ---------------------------------------------------------------------------
// fused fp32 -> fp16 conversion for all 5 input tensors (one launch)
// ---------------------------------------------------------------------------
__global__ void f2h5(const float4* __restrict__ s0, const float4* __restrict__ s1,
                     const float4* __restrict__ s2, const float4* __restrict__ s3,
                     const float4* __restrict__ s4,
                     uint2* __restrict__ d0, uint2* __restrict__ d1,
                     uint2* __restrict__ d2, uint2* __restrict__ d3,
                     uint2* __restrict__ d4) {
    int which = blockIdx.x >> 12;
    int i = (blockIdx.x & 4095) * 256 + threadIdx.x;
    const float4* src = which == 0 ? s0 : which == 1 ? s1 : which == 2 ? s2
                      : which == 3 ? s3 : s4;
    uint2* dst = which == 0 ? d0 : which == 1 ? d1 : which == 2 ? d2
               : which == 3 ? d3 : d4;
    float4 v = src[i];
    __half2 a = __floats2half2_rn(v.x, v.y);
    __half2 b = __floats2half2_rn(v.z, v.w);
    dst[i] = make_uint2(*(uint32_t*)&a, *(uint32_t*)&b);
}

// ---------------------------------------------------------------------------
// RoPE (fast-math-immune)
// ---------------------------------------------------------------------------
__device__ __forceinline__ void sincos_cw(float a, float* sp, float* cp) {
    float j = rintf(a * 0.63661977236758138f);
    int   q = (int)j;
    float r = fmaf(j, -1.5707962512969971e+00f, a);
    r = fmaf(j, -7.5497894158615964e-08f, r);
    r = fmaf(j, -5.3903029534742385e-15f, r);
    float x2 = r * r;
    float s = r * (1.f + x2 * (-1.6666667e-1f + x2 * (8.3333333e-3f +
                    x2 * (-1.9841270e-4f + x2 * 2.7557319e-6f))));
    float c = 1.f + x2 * (-0.5f + x2 * (4.1666667e-2f +
                    x2 * (-1.3888889e-3f + x2 * 2.4801587e-5f)));
    switch (q & 3) {
        case 0: *sp =  s; *cp =  c; break;
        case 1: *sp =  c; *cp = -s; break;
        case 2: *sp = -s; *cp = -c; break;
        default:*sp = -c; *cp =  s; break;
    }
}

__global__ void rope_table() {
    int idx = blockIdx.x * 256 + threadIdx.x;
    int d = idx & 255, t = idx >> 8;
    float e = (float)d * (1.0f / 256.0f);
    const float LH = 13.287712097167969f;
    const float LL = 2.8238148e-7f;
    float p = -fmaf(e, LH, e * LL);
    float nf = floorf(p);
    float f  = p - nf;
    float y  = f * 0.69314718055994531f;
    float er = 1.f + y * (1.f + y * (0.5f + y * (0.16666667f + y * (0.041666667f +
               y * (0.0083333333f + y * (0.0013888889f + y * (1.9841270e-4f +
               y * (2.4801587e-5f + y * 2.7557319e-6f))))))));
    float invf = er * __int_as_float(((int)nf + 127) << 23);
    float ang = (float)t * invf;
    float s, c;
    sincos_cw(ang, &s, &c);
    g_cos[idx] = c;
    g_sin[idx] = s;
}

// In-place RoPE on fp16 q and k halves of g_qkh, half-split pairs.
__global__ void rope_apply() {
    int idx = blockIdx.x * 256 + threadIdx.x;   // B*T*H*Dh
    int d = idx & 255;
    int h = (idx >> 8) & 7;
    int t = (idx >> 11) & 2047;
    int b = idx >> 22;
    float cc = g_cos[t * 256 + d], ss = g_sin[t * 256 + d];
    size_t base = ((size_t)(b * Tt + t)) * HDc + h * Dd + d;
    const size_t KOFF = (size_t)Mc * HDc;
    float x1 = __half2float(g_qkh[base]), x2 = __half2float(g_qkh[base + 256]);
    g_qkh[base]       = __float2half_rn(x1 * cc - x2 * ss);
    g_qkh[base + 256] = __float2half_rn(x1 * ss + x2 * cc);
    x1 = __half2float(g_qkh[KOFF + base]); x2 = __half2float(g_qkh[KOFF + base + 256]);
    g_qkh[KOFF + base]       = __float2half_rn(x1 * cc - x2 * ss);
    g_qkh[KOFF + base + 256] = __float2half_rn(x1 * ss + x2 * cc);
}

// ---------------------------------------------------------------------------
// Causal softmax on fp16 S; zero-pads probs to this row's 128 boundary.
// ---------------------------------------------------------------------------
__global__ void softmax_causal(__half2* __restrict__ S) {
    long long rr = blockIdx.x;
    long long zz = rr >> 11;
    int i = (int)(rr & 2047);
    __half2* row = S + zz * (Tt * Tt / 2) + (size_t)i * (Tt / 2);
    const int L = i + 1;
    const int tid = threadIdx.x;
    __shared__ float red[256];

    float v[8];
    float mx = -3.4e38f;
#pragma unroll
    for (int p = 0; p < 4; p++) {
        int j2 = tid + p * 256;
        float2 f = __half22float2(row[j2]);
        v[p * 2]     = (2 * j2     < L) ? f.x : -3.4e38f;
        v[p * 2 + 1] = (2 * j2 + 1 < L) ? f.y : -3.4e38f;
        mx = fmaxf(mx, fmaxf(v[p * 2], v[p * 2 + 1]));
    }
    red[tid] = mx; __syncthreads();
    for (int s = 128; s > 0; s >>= 1) {
        if (tid < s) red[tid] = fmaxf(red[tid], red[tid + s]);
        __syncthreads();
    }
    mx = red[0]; __syncthreads();

    float sum = 0.f;
#pragma unroll
    for (int p = 0; p < 8; p++) {
        float e = (v[p] > -1e38f) ? expf(v[p] - mx) : 0.f;
        v[p] = e;
        sum += e;
    }
    red[tid] = sum; __syncthreads();
    for (int s = 128; s > 0; s >>= 1) {
        if (tid < s) red[tid] += red[tid + s];
        __syncthreads();
    }
    float inv = 1.0f / red[0];

    const int Lpad = (L + 127) & ~127;
#pragma unroll
    for (int p = 0; p < 4; p++) {
        int j2 = tid + p * 256;
        if (2 * j2 < Lpad)
            row[j2] = __floats2half2_rn(v[p * 2] * inv, v[p * 2 + 1] * inv);
    }
}

// ---------------------------------------------------------------------------
extern "C" void kernel_launch(void* const* d_in, const int* in_sizes, int n_in,
                              void* d_out, int out_size) {
    const float* x  = (const float*)d_in[0];
    const float* Wq = (const float*)d_in[1];
    const float* Wk = (const float*)d_in[2];
    const float* Wv = (const float*)d_in[3];
    const float* Wo = (const float*)d_in[4];
    float* out = (float*)d_out;

    __half *xh, *wqkh, *wvh, *woh, *qkh, *vTh, *attnh, *sh;
    cudaGetSymbolAddress((void**)&xh, g_xh);
    cudaGetSymbolAddress((void**)&wqkh, g_wqkh);
    cudaGetSymbolAddress((void**)&wvh, g_wvh);
    cudaGetSymbolAddress((void**)&woh, g_woh);
    cudaGetSymbolAddress((void**)&qkh, g_qkh);
    cudaGetSymbolAddress((void**)&vTh, g_vTh);
    cudaGetSymbolAddress((void**)&attnh, g_attnh);
    cudaGetSymbolAddress((void**)&sh, g_sh);

    // opt-in smem size AND full shared-memory carveout (needed for 2 CTAs/SM)
    cudaFuncSetAttribute(gemm_fp16<false, false, true>,
                         cudaFuncAttributeMaxDynamicSharedMemorySize, GEMM_SMEM);
    cudaFuncSetAttribute(gemm_fp16<false, false, true>,
                         cudaFuncAttributePreferredSharedMemoryCarveout, 100);
    cudaFuncSetAttribute(gemm_fp16<true, false, true>,
                         cudaFuncAttributeMaxDynamicSharedMemorySize, GEMM_SMEM);
    cudaFuncSetAttribute(gemm_fp16<true, false, true>,
                         cudaFuncAttributePreferredSharedMemoryCarveout, 100);
    cudaFuncSetAttribute(gemm_fp16<false, true, true>,
                         cudaFuncAttributeMaxDynamicSharedMemorySize, GEMM_SMEM);
    cudaFuncSetAttribute(gemm_fp16<false, true, true>,
                         cudaFuncAttributePreferredSharedMemoryCarveout, 100);
    cudaFuncSetAttribute(gemm_fp16<false, false, false>,
                         cudaFuncAttributeMaxDynamicSharedMemorySize, GEMM_SMEM);
    cudaFuncSetAttribute(gemm_fp16<false, false, false>,
                         cudaFuncAttributePreferredSharedMemoryCarveout, 100);

    dim3 blk(256);
    const long long TT  = (long long)Tt * Tt;
    const long long THD = (long long)Tt * HDc;
    const long long WSZ = (long long)HDc * Ee;     // one weight tensor
    const long long QSZ = (long long)Mc * HDc;     // one activation tensor

    // 0) convert raw fp32 inputs to fp16 scratch (single fused launch)
    f2h5<<<5 * 4096, 256>>>((const float4*)x, (const float4*)Wq, (const float4*)Wk,
                            (const float4*)Wv, (const float4*)Wo,
                            (uint2*)xh, (uint2*)wqkh, (uint2*)(wqkh + WSZ),
                            (uint2*)wvh, (uint2*)woh);

    // 1) Q and K projections fused in one launch (z selects Wq/Wk, q/k)
    gemm_fp16<false, false, true><<<dim3(32, 32, 2), blk, GEMM_SMEM>>>(
        xh, wqkh, qkh, Ee, Ee, Ee, HDc,
        0, 0, 0, WSZ, 0, QSZ, 1.f);
    // vT[hd, m] = Wv[hd,:] . x[m,:]
    gemm_fp16<false, false, true><<<dim3(32, 32, 1), blk, GEMM_SMEM>>>(
        wvh, xh, vTh, Ee, Ee, Ee, Mc, 0, 0, 0, 0, 0, 0, 1.f);

    // 2) RoPE on q, k
    rope_table<<<(Tt * Dh) / 256, 256>>>();
    rope_apply<<<(Bb * Tt * Hh * Dh) / 256, 256>>>();

    // 3) scores[b,h] = scale * q[b,h] @ k[b,h]^T   (causal tile skip)
    gemm_fp16<true, false, true><<<dim3(16, 16, Bb * Hh), blk, GEMM_SMEM>>>(
        qkh, qkh + QSZ, sh, Dd, HDc, HDc, Tt,
        THD, (long long)Dd, THD, (long long)Dd,
        (long long)Hh * TT, TT, 0.044194173824159216f);

    // 4) causal softmax (fp16 in/out)
    softmax_causal<<<Bb * Hh * Tt, 256>>>((__half2*)sh);

    // 5) attn[b,h] = P[b,h] @ vT[b,h]^T   (NT, causal K limit)
    gemm_fp16<false, true, true><<<dim3(4, 16, Bb * Hh), blk, GEMM_SMEM>>>(
        sh, vTh, attnh, Tt, Tt, Mc, HDc,
        (long long)Hh * TT, TT,
        (long long)Tt, (long long)Dd * Mc,
        (long long)Tt * HDc, (long long)Dd, 1.f);

    // 6) out = attn_flat @ Wo^T  (fp32 output)
    gemm_fp16<false, false, false><<<dim3(8, 32, 1), blk, GEMM_SMEM>>>(
        attnh, woh, out, HDc, HDc, HDc, Ee, 0, 0, 0, 0, 0, 0, 1.f);
}

// round 12
// speedup vs baseline: 1.2606x; 1.0542x over previous
#include <cuda_runtime.h>
#include <cuda_fp16.h>
#include <cstdint>

// Problem constants
#define Bb  2
#define Tt  2048
#define Ee  1024
#define Hh  8
#define Dd  512
#define HDc 4096          // H*D
#define Mc  4096          // B*T
#define Dh  256           // D/2

// fp16 scratch (static device allocations)
__device__ __align__(1024) __half g_xh[(size_t)Mc * Ee];
__device__ __align__(1024) __half g_wqkh[(size_t)2 * HDc * Ee];   // [Wq | Wk]
__device__ __align__(1024) __half g_wvh[(size_t)HDc * Ee];
__device__ __align__(1024) __half g_woh[(size_t)Ee * HDc];
__device__ __align__(1024) __half g_qkh[(size_t)2 * Mc * HDc];    // [q | k]
__device__ __align__(1024) __half g_vTh[(size_t)HDc * Mc];        // [h*D, b*T]
__device__ __align__(1024) __half g_attnh[(size_t)Mc * HDc];
__device__ __align__(1024) __half g_sh[(size_t)Bb * Hh * Tt * Tt];   // 128 MiB
__device__ float g_cos[Tt * Dh];
__device__ float g_sin[Tt * Dh];

// ---------------------------------------------------------------------------
// PTX helpers
// ---------------------------------------------------------------------------
__device__ __forceinline__ uint32_t smem_u32(const void* p) {
    uint32_t a;
    asm("{ .reg .u64 t; cvta.to.shared.u64 t, %1; cvt.u32.u64 %0, t; }" : "=r"(a) : "l"(p));
    return a;
}
__device__ __forceinline__ void cpasync16(uint32_t dst, const void* src) {
    asm volatile("cp.async.cg.shared.global [%0], [%1], 16;" :: "r"(dst), "l"(src));
}
#define CP_COMMIT() asm volatile("cp.async.commit_group;" ::: "memory")
#define CP_WAIT1()  asm volatile("cp.async.wait_group 1;" ::: "memory")

__device__ __forceinline__ void ldsm4(uint32_t& r0, uint32_t& r1, uint32_t& r2, uint32_t& r3,
                                      uint32_t addr) {
    asm volatile("ldmatrix.sync.aligned.m8n8.x4.shared.b16 {%0,%1,%2,%3}, [%4];"
                 : "=r"(r0), "=r"(r1), "=r"(r2), "=r"(r3) : "r"(addr));
}
__device__ __forceinline__ void mma168(float (&c)[4], const uint32_t (&a)[4], const uint32_t (&b)[2]) {
    asm volatile(
        "mma.sync.aligned.m16n8k16.row.col.f32.f16.f16.f32 "
        "{%0,%1,%2,%3}, {%4,%5,%6,%7}, {%8,%9}, {%0,%1,%2,%3};\n"
        : "+f"(c[0]), "+f"(c[1]), "+f"(c[2]), "+f"(c[3])
        : "r"(a[0]), "r"(a[1]), "r"(a[2]), "r"(a[3]), "r"(b[0]), "r"(b[1]));
}

// Swizzled smem offset for (row, 16B-chunk), 128B rows, full 8-way XOR.
__device__ __forceinline__ uint32_t swz(int r, int c) {
    return (uint32_t)(r * 128 + ((c ^ (r & 7)) << 4));
}

// ---------------------------------------------------------------------------
// fp16 tensor-core GEMM:  C = alpha * A[M,K] * B[N,K]^T   (both K-major, NT)
// CSKIP: skip tiles strictly above causal diagonal.  CK: limit K to m0+128.
// OUT16: store C as fp16 (else fp32).  REV: reverse y-order (heavy tiles
// first, for causally K-limited launches).
// CTA tile 128x128, K-chunk 64, 128 threads, 4 warps (2m x 2n), warp 64x64,
// 3-stage cp.async pipeline (32KB/stage), one sync per chunk, 2 CTAs/SM.
// Batch over blockIdx.z: off = (z>>3)*Outer + (z&7)*Inner.
// ---------------------------------------------------------------------------
#define NSTG   3
#define STG_B  32768                        // A 128*128B + B 128*128B
#define GEMM_SMEM (NSTG * STG_B)            // 98304 -> 2 CTAs/SM (192KB)

template <bool CSKIP, bool CK, bool OUT16, bool REV>
__global__ __launch_bounds__(128, 2) void gemm_fp16(
    const __half* __restrict__ Ag, const __half* __restrict__ Bg, void* __restrict__ Cg,
    int Kdim, int lda, int ldb, int ldc,
    long long aO, long long aI, long long bO, long long bI, long long cO, long long cI,
    float alpha)
{
    const int my = REV ? (gridDim.y - 1 - blockIdx.y) : blockIdx.y;
    const int m0 = my * 128;
    const int n0 = blockIdx.x * 128;
    if (CSKIP && n0 >= m0 + 128) return;

    const int z = blockIdx.z;
    const __half* A = Ag + (long long)(z >> 3) * aO + (long long)(z & 7) * aI;
    const __half* B = Bg + (long long)(z >> 3) * bO + (long long)(z & 7) * bI;

    const int kLim = CK ? ((Kdim < m0 + 128) ? Kdim : (m0 + 128)) : Kdim;
    const int nk = kLim >> 6;               // 64-wide K chunks

    extern __shared__ char smem[];
    const uint32_t sb = smem_u32(smem);
    const int tid = threadIdx.x, wid = tid >> 5, lane = tid & 31;
    const int wm = wid & 1, wn = wid >> 1;   // 2m x 2n warp grid

    const int ldr = tid >> 3;                // row group 0..15 (x8 -> 128 rows)
    const int ldc8 = tid & 7;                // 16B chunk 0..7 within 128B row
    auto load_stage = [&](int kt) {
        uint32_t stA = sb + (kt % NSTG) * STG_B;
        uint32_t stB = stA + 16384;
        const __half* Asrc = A + (size_t)m0 * lda + kt * 64;
        const __half* Bsrc = B + (size_t)n0 * ldb + kt * 64;
#pragma unroll
        for (int p = 0; p < 8; p++) {
            int r = ldr + p * 16;
            cpasync16(stA + swz(r, ldc8), Asrc + (size_t)r * lda + ldc8 * 8);
        }
#pragma unroll
        for (int p = 0; p < 8; p++) {
            int r = ldr + p * 16;
            cpasync16(stB + swz(r, ldc8), Bsrc + (size_t)r * ldb + ldc8 * 8);
        }
    };

#pragma unroll
    for (int s = 0; s < NSTG - 1; s++) { if (s < nk) load_stage(s); CP_COMMIT(); }

    float acc[4][8][4] = {};

    const int lrow = lane & 15;
    const int chHalf = lane >> 4;

    for (int kt = 0; kt < nk; kt++) {
        CP_WAIT1();
        __syncthreads();
        if (kt + NSTG - 1 < nk) load_stage(kt + NSTG - 1);
        CP_COMMIT();

        uint32_t stA = sb + (kt % NSTG) * STG_B;
        uint32_t stB = stA + 16384;
#pragma unroll
        for (int kk = 0; kk < 4; kk++) {
            const int ch = kk * 2 + chHalf;
            uint32_t a[4][4], b[8][2];
#pragma unroll
            for (int i = 0; i < 4; i++) {
                int r = wm * 64 + i * 16 + lrow;
                ldsm4(a[i][0], a[i][1], a[i][2], a[i][3], stA + swz(r, ch));
            }
#pragma unroll
            for (int jp = 0; jp < 4; jp++) {
                int r = wn * 64 + jp * 16 + lrow;
                uint32_t t0, t1, t2, t3;
                ldsm4(t0, t1, t2, t3, stB + swz(r, ch));
                b[jp * 2][0] = t0; b[jp * 2 + 1][0] = t1;
                b[jp * 2][1] = t2; b[jp * 2 + 1][1] = t3;
            }
#pragma unroll
            for (int i = 0; i < 4; i++)
#pragma unroll
                for (int j = 0; j < 8; j++) mma168(acc[i][j], a[i], b[j]);
        }
    }

    const int er = lane >> 2, ec = (lane & 3) * 2;
    if (OUT16) {
        __half* C = (__half*)Cg + (long long)(z >> 3) * cO + (long long)(z & 7) * cI;
#pragma unroll
        for (int i = 0; i < 4; i++) {
            int r0 = m0 + wm * 64 + i * 16 + er;
#pragma unroll
            for (int j = 0; j < 8; j++) {
                int c0 = n0 + wn * 64 + j * 8 + ec;
                __half2 h01 = __floats2half2_rn(acc[i][j][0] * alpha, acc[i][j][1] * alpha);
                __half2 h23 = __floats2half2_rn(acc[i][j][2] * alpha, acc[i][j][3] * alpha);
                *(__half2*)(C + (size_t)r0 * ldc + c0) = h01;
                *(__half2*)(C + (size_t)(r0 + 8) * ldc + c0) = h23;
            }
        }
    } else {
        float* C = (float*)Cg + (long long)(z >> 3) * cO + (long long)(z & 7) * cI;
#pragma unroll
        for (int i = 0; i < 4; i++) {
            int r0 = m0 + wm * 64 + i * 16 + er;
#pragma unroll
            for (int j = 0; j < 8; j++) {
                int c0 = n0 + wn * 64 + j * 8 + ec;
                *(float2*)(C + (size_t)r0 * ldc + c0) =
                    make_float2(acc[i][j][0] * alpha, acc[i][j][1] * alpha);
                *(float2*)(C + (size_t)(r0 + 8) * ldc + c0) =
                    make_float2(acc[i][j][2] * alpha, acc[i][j][3] * alpha);
            }
        }
    }
}

// ---------------------------------------------------------------------------
// fused fp32 -> fp16 conversion for all 5 input tensors, 4 float4 per thread
// ---------------------------------------------------------------------------
__global__ void f2h5(const float4* __restrict__ s0, const float4* __restrict__ s1,
                     const float4* __restrict__ s2, const float4* __restrict__ s3,
                     const float4* __restrict__ s4,
                     uint2* __restrict__ d0, uint2* __restrict__ d1,
                     uint2* __restrict__ d2, uint2* __restrict__ d3,
                     uint2* __restrict__ d4) {
    int which = blockIdx.x >> 10;            // 1024 blocks per tensor
    int base = (blockIdx.x & 1023) * 1024 + threadIdx.x;
    const float4* src = which == 0 ? s0 : which == 1 ? s1 : which == 2 ? s2
                      : which == 3 ? s3 : s4;
    uint2* dst = which == 0 ? d0 : which == 1 ? d1 : which == 2 ? d2
               : which == 3 ? d3 : d4;
    float4 v[4];
#pragma unroll
    for (int p = 0; p < 4; p++) v[p] = src[base + p * 256];
#pragma unroll
    for (int p = 0; p < 4; p++) {
        __half2 a = __floats2half2_rn(v[p].x, v[p].y);
        __half2 b = __floats2half2_rn(v[p].z, v[p].w);
        dst[base + p * 256] = make_uint2(*(uint32_t*)&a, *(uint32_t*)&b);
    }
}

// ---------------------------------------------------------------------------
// RoPE (fast-math-immune)
// ---------------------------------------------------------------------------
__device__ __forceinline__ void sincos_cw(float a, float* sp, float* cp) {
    float j = rintf(a * 0.63661977236758138f);
    int   q = (int)j;
    float r = fmaf(j, -1.5707962512969971e+00f, a);
    r = fmaf(j, -7.5497894158615964e-08f, r);
    r = fmaf(j, -5.3903029534742385e-15f, r);
    float x2 = r * r;
    float s = r * (1.f + x2 * (-1.6666667e-1f + x2 * (8.3333333e-3f +
                    x2 * (-1.9841270e-4f + x2 * 2.7557319e-6f))));
    float c = 1.f + x2 * (-0.5f + x2 * (4.1666667e-2f +
                    x2 * (-1.3888889e-3f + x2 * 2.4801587e-5f)));
    switch (q & 3) {
        case 0: *sp =  s; *cp =  c; break;
        case 1: *sp =  c; *cp = -s; break;
        case 2: *sp = -s; *cp = -c; break;
        default:*sp = -c; *cp =  s; break;
    }
}

__global__ void rope_table() {
    int idx = blockIdx.x * 256 + threadIdx.x;
    int d = idx & 255, t = idx >> 8;
    float e = (float)d * (1.0f / 256.0f);
    const float LH = 13.287712097167969f;
    const float LL = 2.8238148e-7f;
    float p = -fmaf(e, LH, e * LL);
    float nf = floorf(p);
    float f  = p - nf;
    float y  = f * 0.69314718055994531f;
    float er = 1.f + y * (1.f + y * (0.5f + y * (0.16666667f + y * (0.041666667f +
               y * (0.0083333333f + y * (0.0013888889f + y * (1.9841270e-4f +
               y * (2.4801587e-5f + y * 2.7557319e-6f))))))));
    float invf = er * __int_as_float(((int)nf + 127) << 23);
    float ang = (float)t * invf;
    float s, c;
    sincos_cw(ang, &s, &c);
    g_cos[idx] = c;
    g_sin[idx] = s;
}

// In-place RoPE on fp16 q and k halves of g_qkh; 2 freq-pairs per thread.
__global__ void rope_apply() {
    int idx = blockIdx.x * 256 + threadIdx.x;   // B*T*H*128 threads
    int dp = idx & 127;                          // pair-of-pairs index
    int h = (idx >> 7) & 7;
    int t = (idx >> 10) & 2047;
    int b = idx >> 21;
    float2 cs0 = *(const float2*)&g_cos[t * 256 + dp * 2];
    float2 sn0 = *(const float2*)&g_sin[t * 256 + dp * 2];
    size_t base = ((size_t)(b * Tt + t)) * HDc + h * Dd + dp * 2;
    const size_t KOFF = (size_t)Mc * HDc;
#pragma unroll
    for (int w = 0; w < 2; w++) {
        __half* g = (__half*)g_qkh + w * KOFF;
        float2 x1 = __half22float2(*(__half2*)(g + base));
        float2 x2 = __half22float2(*(__half2*)(g + base + 256));
        __half2 o1 = __floats2half2_rn(x1.x * cs0.x - x2.x * sn0.x,
                                       x1.y * cs0.y - x2.y * sn0.y);
        __half2 o2 = __floats2half2_rn(x1.x * sn0.x + x2.x * cs0.x,
                                       x1.y * sn0.y + x2.y * cs0.y);
        *(__half2*)(g + base) = o1;
        *(__half2*)(g + base + 256) = o2;
    }
}

// ---------------------------------------------------------------------------
// Causal softmax on fp16 S; zero-pads probs to this row's 128 boundary.
// ---------------------------------------------------------------------------
__global__ void softmax_causal(__half2* __restrict__ S) {
    long long rr = blockIdx.x;
    long long zz = rr >> 11;
    int i = (int)(rr & 2047);
    __half2* row = S + zz * (Tt * Tt / 2) + (size_t)i * (Tt / 2);
    const int L = i + 1;
    const int tid = threadIdx.x;
    __shared__ float red[256];

    float v[8];
    float mx = -3.4e38f;
#pragma unroll
    for (int p = 0; p < 4; p++) {
        int j2 = tid + p * 256;
        float2 f = __half22float2(row[j2]);
        v[p * 2]     = (2 * j2     < L) ? f.x : -3.4e38f;
        v[p * 2 + 1] = (2 * j2 + 1 < L) ? f.y : -3.4e38f;
        mx = fmaxf(mx, fmaxf(v[p * 2], v[p * 2 + 1]));
    }
    red[tid] = mx; __syncthreads();
    for (int s = 128; s > 0; s >>= 1) {
        if (tid < s) red[tid] = fmaxf(red[tid], red[tid + s]);
        __syncthreads();
    }
    mx = red[0]; __syncthreads();

    float sum = 0.f;
#pragma unroll
    for (int p = 0; p < 8; p++) {
        float e = (v[p] > -1e38f) ? expf(v[p] - mx) : 0.f;
        v[p] = e;
        sum += e;
    }
    red[tid] = sum; __syncthreads();
    for (int s = 128; s > 0; s >>= 1) {
        if (tid < s) red[tid] += red[tid + s];
        __syncthreads();
    }
    float inv = 1.0f / red[0];

    const int Lpad = (L + 127) & ~127;
#pragma unroll
    for (int p = 0; p < 4; p++) {
        int j2 = tid + p * 256;
        if (2 * j2 < Lpad)
            row[j2] = __floats2half2_rn(v[p * 2] * inv, v[p * 2 + 1] * inv);
    }
}

// ---------------------------------------------------------------------------
extern "C" void kernel_launch(void* const* d_in, const int* in_sizes, int n_in,
                              void* d_out, int out_size) {
    const float* x  = (const float*)d_in[0];
    const float* Wq = (const float*)d_in[1];
    const float* Wk = (const float*)d_in[2];
    const float* Wv = (const float*)d_in[3];
    const float* Wo = (const float*)d_in[4];
    float* out = (float*)d_out;

    __half *xh, *wqkh, *wvh, *woh, *qkh, *vTh, *attnh, *sh;
    cudaGetSymbolAddress((void**)&xh, g_xh);
    cudaGetSymbolAddress((void**)&wqkh, g_wqkh);
    cudaGetSymbolAddress((void**)&wvh, g_wvh);
    cudaGetSymbolAddress((void**)&woh, g_woh);
    cudaGetSymbolAddress((void**)&qkh, g_qkh);
    cudaGetSymbolAddress((void**)&vTh, g_vTh);
    cudaGetSymbolAddress((void**)&attnh, g_attnh);
    cudaGetSymbolAddress((void**)&sh, g_sh);

    cudaFuncSetAttribute(gemm_fp16<false, false, true, false>,
                         cudaFuncAttributeMaxDynamicSharedMemorySize, GEMM_SMEM);
    cudaFuncSetAttribute(gemm_fp16<false, false, true, false>,
                         cudaFuncAttributePreferredSharedMemoryCarveout, 100);
    cudaFuncSetAttribute(gemm_fp16<true, false, true, false>,
                         cudaFuncAttributeMaxDynamicSharedMemorySize, GEMM_SMEM);
    cudaFuncSetAttribute(gemm_fp16<true, false, true, false>,
                         cudaFuncAttributePreferredSharedMemoryCarveout, 100);
    cudaFuncSetAttribute(gemm_fp16<false, true, true, true>,
                         cudaFuncAttributeMaxDynamicSharedMemorySize, GEMM_SMEM);
    cudaFuncSetAttribute(gemm_fp16<false, true, true, true>,
                         cudaFuncAttributePreferredSharedMemoryCarveout, 100);
    cudaFuncSetAttribute(gemm_fp16<false, false, false, false>,
                         cudaFuncAttributeMaxDynamicSharedMemorySize, GEMM_SMEM);
    cudaFuncSetAttribute(gemm_fp16<false, false, false, false>,
                         cudaFuncAttributePreferredSharedMemoryCarveout, 100);

    dim3 blk(128);
    const long long TT  = (long long)Tt * Tt;
    const long long THD = (long long)Tt * HDc;
    const long long WSZ = (long long)HDc * Ee;     // one weight tensor
    const long long QSZ = (long long)Mc * HDc;     // one activation tensor

    // 0) convert raw fp32 inputs to fp16 scratch (single fused launch, 4x ILP)
    f2h5<<<5 * 1024, 256>>>((const float4*)x, (const float4*)Wq, (const float4*)Wk,
                            (const float4*)Wv, (const float4*)Wo,
                            (uint2*)xh, (uint2*)wqkh, (uint2*)(wqkh + WSZ),
                            (uint2*)wvh, (uint2*)woh);

    // 1) Q and K projections fused in one launch (z selects Wq/Wk, q/k)
    gemm_fp16<false, false, true, false><<<dim3(32, 32, 2), blk, GEMM_SMEM>>>(
        xh, wqkh, qkh, Ee, Ee, Ee, HDc,
        0, 0, 0, WSZ, 0, QSZ, 1.f);
    // vT[hd, m] = Wv[hd,:] . x[m,:]
    gemm_fp16<false, false, true, false><<<dim3(32, 32, 1), blk, GEMM_SMEM>>>(
        wvh, xh, vTh, Ee, Ee, Ee, Mc, 0, 0, 0, 0, 0, 0, 1.f);

    // 2) RoPE on q, k
    rope_table<<<(Tt * Dh) / 256, 256>>>();
    rope_apply<<<(Bb * Tt * Hh * 128) / 256, 256>>>();

    // 3) scores[b,h] = scale * q[b,h] @ k[b,h]^T   (causal tile skip)
    gemm_fp16<true, false, true, false><<<dim3(16, 16, Bb * Hh), blk, GEMM_SMEM>>>(
        qkh, qkh + QSZ, sh, Dd, HDc, HDc, Tt,
        THD, (long long)Dd, THD, (long long)Dd,
        (long long)Hh * TT, TT, 0.044194173824159216f);

    // 4) causal softmax (fp16 in/out)
    softmax_causal<<<Bb * Hh * Tt, 256>>>((__half2*)sh);

    // 5) attn[b,h] = P[b,h] @ vT[b,h]^T   (NT, causal K limit, heavy-first)
    gemm_fp16<false, true, true, true><<<dim3(4, 16, Bb * Hh), blk, GEMM_SMEM>>>(
        sh, vTh, attnh, Tt, Tt, Mc, HDc,
        (long long)Hh * TT, TT,
        (long long)Tt, (long long)Dd * Mc,
        (long long)Tt * HDc, (long long)Dd, 1.f);

    // 6) out = attn_flat @ Wo^T  (fp32 output)
    gemm_fp16<false, false, false, false><<<dim3(8, 32, 1), blk, GEMM_SMEM>>>(
        attnh, woh, out, HDc, HDc, HDc, Ee, 0, 0, 0, 0, 0, 0, 1.f);
}